// round 17
// baseline (speedup 1.0000x reference)
#include <cuda_runtime.h>
#include <cuda_fp16.h>
#include <cstdint>

// ---------------------------------------------------------------------------
// TargetTokenEncoder: hist/stats -> MLP(14->256, exact GELU) -> GEMM(256x256)
// Both GEMMs on tensor cores (mma.sync m16n8k16 f16, fp32 accum):
//   stage B: stats(fp16, exact except entropy) @ w1(fp16 hi+lo, 2 passes)
//   stage C: h(fp16) @ w2(fp16, 1 pass)           rel err ~3e-4 total
// R17: R16 + (a) A&S-7.1.26 erf (1.5e-7 abs err, ~half the instrs of erff),
//      (b) b1/b2 loads hoisted out of the m-tile loops (were 4x redundant),
//      (c) simple 1-ahead B prefetch (R16 showed depth is not binding).
// ---------------------------------------------------------------------------

static constexpr int S      = 128;
static constexpr int TD     = 256;
static constexpr int TILE_M = 64;

static constexpr int A_STRIDE = 528;     // 256 fp16 + 8 pad
static constexpr int OFF_A     = 0;      // 64 x 528 = 33792
static constexpr int OFF_STATS = 33792;  // 64 rows x 48B
static constexpr int STATS_STRIDE = 48;  // 16B multiple (ldmatrix-legal)
static constexpr int SMEM_BYTES = 36864; // x2 CTAs = 73728

// w2 fragment scratch: [ks 0..15][cgpair 0..15][lane 0..31][8 fp16]
// Element (e): cg = 2*cgp + (e>>2), k = ks*16 + 2*(L%4) + ((e&2)?8:0) + (e&1),
//              n = cg*8 + L/4, value = w2[k][n]. (layout verified R7..R16)
__device__ __align__(16) __half g_b[16 * 16 * 32 * 8];     // 128KB
// w1 fragment scratch (single ks, K=16 with rows 14,15 zero): hi + lo planes
__device__ __align__(16) __half g_w1h[16 * 32 * 8];        // 8KB
__device__ __align__(16) __half g_w1l[16 * 32 * 8];        // 8KB

__device__ __forceinline__ uint32_t smem_u32(const void* p) {
    uint32_t a;
    asm("{ .reg .u64 t; cvta.to.shared.u64 t, %1; cvt.u32.u64 %0, t; }" : "=r"(a) : "l"(p));
    return a;
}

__device__ __forceinline__ void ldm4(uint32_t* r, uint32_t addr) {
    asm volatile("ldmatrix.sync.aligned.m8n8.x4.shared.b16 {%0,%1,%2,%3}, [%4];"
                 : "=r"(r[0]), "=r"(r[1]), "=r"(r[2]), "=r"(r[3]) : "r"(addr));
}

__device__ __forceinline__ void mma_f16(float* c, const uint32_t* a,
                                        uint32_t b0, uint32_t b1) {
    asm volatile("mma.sync.aligned.m16n8k16.row.col.f32.f16.f16.f32 "
                 "{%0,%1,%2,%3}, {%4,%5,%6,%7}, {%8,%9}, {%0,%1,%2,%3};"
                 : "+f"(c[0]), "+f"(c[1]), "+f"(c[2]), "+f"(c[3])
                 : "r"(a[0]), "r"(a[1]), "r"(a[2]), "r"(a[3]), "r"(b0), "r"(b1));
}

// exact-accuracy GELU: erf via Abramowitz-Stegun 7.1.26 (max abs err 1.5e-7,
// ~1e-7 relative effect on output — far below the 3e-4 fp16 split error).
__device__ __forceinline__ float gelu_exact(float x) {
    const float z  = x * 0.70710678118654752440f;
    const float az = fabsf(z);
    const float t  = __fdividef(1.0f, fmaf(0.3275911f, az, 1.0f));
    const float e  = __expf(-z * z);
    float p = fmaf(1.061405429f, t, -1.453152027f);
    p = fmaf(p, t, 1.421413741f);
    p = fmaf(p, t, -0.284496736f);
    p = fmaf(p, t, 0.254829592f);
    p = p * t;
    float er = copysignf(fmaf(-p, e, 1.0f), z);
    const float hx = 0.5f * x;
    return fmaf(hx, er, hx);
}

// ---------------- fused prep: w2 + w1 -> fp16 fragment scratch (wide)
__global__ __launch_bounds__(256)
void prep_all(const float* __restrict__ w2, const float* __restrict__ w1) {
    const int t = blockIdx.x * 256 + threadIdx.x;      // 0..32767
    {
        const int el  = t * 2;
        const int grp = el >> 3;                       // (ks<<9)|(cgp<<5)|L
        const int e0  = el & 7;
        const int L   = grp & 31;
        const int cgp = (grp >> 5) & 15;
        const int ks  = grp >> 9;
        const int cg  = cgp * 2 + (e0 >> 2);
        const int n   = cg * 8 + (L >> 2);
        const int kk0 = ks * 16 + 2 * (L & 3) + ((e0 & 2) ? 8 : 0);
        const float v0 = __ldg(w2 + (size_t)kk0 * TD + n);
        const float v1 = __ldg(w2 + (size_t)(kk0 + 1) * TD + n);
        reinterpret_cast<__half2*>(g_b)[t] = __floats2half2_rn(v0, v1);
    }
    if (t < 2048) {                                    // w1 frags: 2048 half2/plane
        const int el  = t * 2;
        const int grp = el >> 3;                       // (cgp<<5)|L
        const int e0  = el & 7;
        const int L   = grp & 31;
        const int cgp = grp >> 5;
        const int cg  = cgp * 2 + (e0 >> 2);
        const int n   = cg * 8 + (L >> 2);
        const int kk0 = 2 * (L & 3) + ((e0 & 2) ? 8 : 0);
        const float v0 = (kk0 < 14)     ? __ldg(w1 + (size_t)kk0 * TD + n) : 0.0f;
        const float v1 = (kk0 + 1 < 14) ? __ldg(w1 + (size_t)(kk0 + 1) * TD + n) : 0.0f;
        const __half h0 = __float2half_rn(v0), h1 = __float2half_rn(v1);
        reinterpret_cast<__half2*>(g_w1h)[t] = __halves2half2(h0, h1);
        reinterpret_cast<__half2*>(g_w1l)[t] =
            __floats2half2_rn(v0 - __half2float(h0), v1 - __half2float(h1));
    }
}

__global__ __launch_bounds__(256, 2)
void tte_kernel(const int* __restrict__ y,
                const float* __restrict__ b1,
                const float* __restrict__ b2, float* __restrict__ out)
{
    extern __shared__ char smem[];
    const uint32_t sb = smem_u32(smem);
    const int tid = threadIdx.x;
    const int wid = tid >> 5;
    const int lid = tid & 31;

    // ---------------- Phase 1: cooperative histogram, 4 threads per row
    {
        const int row = tid >> 2;             // 0..63
        const int sub = tid & 3;
        const int4* p = reinterpret_cast<const int4*>(
            y + ((size_t)blockIdx.x * TILE_M + row) * S) + sub * 8;
        uint32_t a0 = 0, a1 = 0, a2 = 0;      // 4x8-bit packed counters
        #pragma unroll
        for (int i = 0; i < 8; i++) {
            int4 v = __ldg(p + i);
            { int x = v.x; uint32_t b = 1u << ((x & 3) << 3);
              if (x < 4) a0 += b; else if (x < 8) a1 += b; else a2 += b; }
            { int x = v.y; uint32_t b = 1u << ((x & 3) << 3);
              if (x < 4) a0 += b; else if (x < 8) a1 += b; else a2 += b; }
            { int x = v.z; uint32_t b = 1u << ((x & 3) << 3);
              if (x < 4) a0 += b; else if (x < 8) a1 += b; else a2 += b; }
            { int x = v.w; uint32_t b = 1u << ((x & 3) << 3);
              if (x < 4) a0 += b; else if (x < 8) a1 += b; else a2 += b; }
        }
        a0 += __shfl_xor_sync(0xFFFFFFFFu, a0, 1);
        a1 += __shfl_xor_sync(0xFFFFFFFFu, a1, 1);
        a2 += __shfl_xor_sync(0xFFFFFFFFu, a2, 1);
        a0 += __shfl_xor_sync(0xFFFFFFFFu, a0, 2);
        a1 += __shfl_xor_sync(0xFFFFFFFFu, a1, 2);
        a2 += __shfl_xor_sync(0xFFFFFFFFu, a2, 2);
        if (sub == 0) {
            int cnt[10];
            float pr[10];
            #pragma unroll
            for (int c = 0; c < 10; c++) {
                uint32_t a = (c < 4) ? a0 : ((c < 8) ? a1 : a2);
                cnt[c] = (int)((a >> ((c & 3) * 8)) & 0xFF);
                pr[c]  = (float)cnt[c] * (1.0f / 128.0f);   // exact in fp32/fp16
            }
            float ent = 0.0f, pm = 0.0f, nnz = 0.0f;
            #pragma unroll
            for (int c = 0; c < 10; c++) {
                ent -= pr[c] * logf(pr[c] + 1e-6f);         // p==0 -> exactly 0
                pm   = fmaxf(pm, pr[c]);
                nnz += (cnt[c] > 0) ? 1.0f : 0.0f;
            }
            __half2* sr = reinterpret_cast<__half2*>(smem + OFF_STATS
                                                     + row * STATS_STRIDE);
            sr[0] = __floats2half2_rn(pr[0], pr[1]);
            sr[1] = __floats2half2_rn(pr[2], pr[3]);
            sr[2] = __floats2half2_rn(pr[4], pr[5]);
            sr[3] = __floats2half2_rn(pr[6], pr[7]);
            sr[4] = __floats2half2_rn(pr[8], pr[9]);
            sr[5] = __floats2half2_rn(nnz, ent);
            sr[6] = __floats2half2_rn(128.0f, pm);
            sr[7] = __floats2half2_rn(0.0f, 0.0f);
        }
    }
    __syncthreads();

    // warp/lane geometry shared by both GEMMs
    const int wn = wid;                // warp owns cols [wn*32, wn*32+32)
    const int j8 = lid >> 3;
    const int lr = lid & 7;
    const int g  = lid >> 2;
    const int tg = lid & 3;

    // ---------------- Phase 2: stage B = stats[64,16] @ w1[16,256] via HMMA,
    //                  + b1, exact GELU, h -> A smem (fp16)
    {
        const uint4* gwh = reinterpret_cast<const uint4*>(g_w1h);
        const uint4* gwl = reinterpret_cast<const uint4*>(g_w1l);
        uint4 fh[2], fl[2];
        float2 bv[4];                      // b1 cols depend on cg only: hoist
        #pragma unroll
        for (int c = 0; c < 2; c++) {
            fh[c] = __ldg(gwh + (((wn * 2 + c) << 5) + lid));
            fl[c] = __ldg(gwl + (((wn * 2 + c) << 5) + lid));
        }
        #pragma unroll
        for (int cg = 0; cg < 4; cg++)
            bv[cg] = __ldg(reinterpret_cast<const float2*>(
                b1 + wn * 32 + cg * 8 + tg * 2));
        #pragma unroll
        for (int i = 0; i < 4; i++) {      // 4 m-tiles of 16 rows
            uint32_t afS[4];
            const uint32_t ad = sb + OFF_STATS
                + (uint32_t)((i * 16 + ((j8 & 1) << 3) + lr) * STATS_STRIDE)
                + (uint32_t)((j8 >> 1) << 4);
            ldm4(afS, ad);
            #pragma unroll
            for (int cg = 0; cg < 4; cg++) {
                float accS[4] = {0.0f, 0.0f, 0.0f, 0.0f};
                const uint4& bh = fh[cg >> 1];
                const uint4& bl = fl[cg >> 1];
                const uint32_t h0 = (cg & 1) ? bh.z : bh.x;
                const uint32_t h1 = (cg & 1) ? bh.w : bh.y;
                const uint32_t l0 = (cg & 1) ? bl.z : bl.x;
                const uint32_t l1 = (cg & 1) ? bl.w : bl.y;
                mma_f16(accS, afS, h0, h1);   // S*W1h
                mma_f16(accS, afS, l0, l1);   // S*W1l
                const int col = wn * 32 + cg * 8 + tg * 2;
                const int r0 = i * 16 + g;
                *reinterpret_cast<__half2*>(smem + OFF_A
                    + (uint32_t)(r0 * A_STRIDE + col * 2)) =
                    __floats2half2_rn(gelu_exact(accS[0] + bv[cg].x),
                                      gelu_exact(accS[1] + bv[cg].y));
                *reinterpret_cast<__half2*>(smem + OFF_A
                    + (uint32_t)((r0 + 8) * A_STRIDE + col * 2)) =
                    __floats2half2_rn(gelu_exact(accS[2] + bv[cg].x),
                                      gelu_exact(accS[3] + bv[cg].y));
            }
        }
    }
    __syncthreads();   // last barrier — stage C runs barrier-free

    // ---------------- Phase 3: GEMM h[64,256] @ w2 slice, fp16 HMMA (1 pass)
    uint32_t aoff[4];
    #pragma unroll
    for (int i = 0; i < 4; i++)
        aoff[i] = sb + OFF_A
                + (uint32_t)((i * 16 + ((j8 & 1) << 3) + lr) * A_STRIDE)
                + (uint32_t)((j8 >> 1) << 4);

    const uint4* gb = reinterpret_cast<const uint4*>(g_b);

    float acc[4][4][4];                // [mtile][cg][frag] = 64 regs
    #pragma unroll
    for (int i = 0; i < 4; i++)
        #pragma unroll
        for (int j = 0; j < 4; j++)
            #pragma unroll
            for (int q = 0; q < 4; q++) acc[i][j][q] = 0.0f;

    uint4 fB[2];
    #pragma unroll
    for (int c = 0; c < 2; c++)
        fB[c] = __ldg(gb + (((wn * 2 + c) << 5) + lid));

    #pragma unroll
    for (int ks = 0; ks < 16; ks++) {
        uint4 nB[2];
        if (ks < 15) {
            #pragma unroll
            for (int c = 0; c < 2; c++)
                nB[c] = __ldg(gb + ((((ks + 1) * 16 + wn * 2 + c) << 5) + lid));
        }
        const uint32_t ka = (uint32_t)(ks * 32);
        uint32_t af[4][4];
        #pragma unroll
        for (int i = 0; i < 4; i++) ldm4(af[i], aoff[i] + ka);
        #pragma unroll
        for (int i = 0; i < 4; i++) {
            #pragma unroll
            for (int cg = 0; cg < 4; cg++) {
                const uint4& bh = fB[cg >> 1];
                const uint32_t b0 = (cg & 1) ? bh.z : bh.x;
                const uint32_t b1v = (cg & 1) ? bh.w : bh.y;
                mma_f16(acc[i][cg], af[i], b0, b1v);
            }
        }
        #pragma unroll
        for (int c = 0; c < 2; c++) fB[c] = nB[c];
    }

    // ---------------- Epilogue (b2 hoisted: cols depend on cg only)
    {
        float2 bbv[4];
        #pragma unroll
        for (int cg = 0; cg < 4; cg++)
            bbv[cg] = __ldg(reinterpret_cast<const float2*>(
                b2 + wn * 32 + cg * 8 + tg * 2));
        const size_t rbase = (size_t)blockIdx.x * TILE_M;
        #pragma unroll
        for (int i = 0; i < 4; i++) {
            #pragma unroll
            for (int cg = 0; cg < 4; cg++) {
                const int col = wn * 32 + cg * 8 + tg * 2;
                const size_t r0 = rbase + i * 16 + g;
                *reinterpret_cast<float2*>(out + r0 * TD + col) =
                    make_float2(acc[i][cg][0] + bbv[cg].x, acc[i][cg][1] + bbv[cg].y);
                *reinterpret_cast<float2*>(out + (r0 + 8) * TD + col) =
                    make_float2(acc[i][cg][2] + bbv[cg].x, acc[i][cg][3] + bbv[cg].y);
            }
        }
    }
}

extern "C" void kernel_launch(void* const* d_in, const int* in_sizes, int n_in,
                              void* d_out, int out_size) {
    const int*   y  = (const int*)d_in[0];
    const float* w1 = (const float*)d_in[1];
    const float* b1 = (const float*)d_in[2];
    const float* w2 = (const float*)d_in[3];
    const float* b2 = (const float*)d_in[4];
    float* out = (float*)d_out;
    const int Btot = in_sizes[0] / S;          // 65536 rows
    const int grid = Btot / TILE_M;            // 1024 CTAs

    prep_all<<<128, 256>>>(w2, w1);            // fused wide prep (~2us)

    cudaFuncSetAttribute(tte_kernel, cudaFuncAttributeMaxDynamicSharedMemorySize,
                         SMEM_BYTES);
    tte_kernel<<<grid, 256, SMEM_BYTES>>>(y, b1, b2, out);
}